// round 1
// baseline (speedup 1.0000x reference)
#include <cuda_runtime.h>

#define GRIDW 480
#define NBATCH 4
#define NPTS 100000
#define PTOT 400000
#define NCELL (NBATCH*GRIDW*GRIDW)   // 921600
#define TILE 128
#define NTILES (PTOT/TILE)           // 3125
#define NT 256

// ---------------- shared memory layout (float offsets) ----------------
#define S_W2   0        // 128*256 = 32768
#define S_H1   32768    // 128*128 = 16384  (layout [i][pt])
#define S_H2   49152    // 32*128  = 4096   (layout [jloc][pt])
#define S_W3C  53248    // 32*64   = 2048   (per-chunk W3 slice)
#define S_W1   55296    // 3*128   = 384
#define S_B1   55680    // 128
#define S_B2   55808    // 256
#define S_B3   56064    // 64
#define S_XS   56128    // 128*3   = 384
#define S_RANK 56512    // 128 (ints)
#define SMEM_FLOATS 56640
#define SMEM_BYTES (SMEM_FLOATS*4)   // 226560 B < 232448 B limit

// ---------------- device scratch (static, allocation-free) ----------------
__device__ unsigned char g_flags[NCELL];
__device__ int g_rank[NCELL];
__device__ int g_bsum[1024];

// ---------------- packed f32x2 helpers ----------------
__device__ __forceinline__ unsigned long long dup2(float a) {
    unsigned long long r;
    asm("mov.b64 %0, {%1, %1};" : "=l"(r) : "f"(a));
    return r;
}
__device__ __forceinline__ void fma2(unsigned long long& d, unsigned long long a,
                                     unsigned long long b) {
    asm("fma.rn.f32x2 %0, %1, %2, %0;" : "+l"(d) : "l"(a), "l"(b));
}
__device__ __forceinline__ void upk2(unsigned long long v, float& a, float& b) {
    asm("mov.b64 {%0, %1}, %2;" : "=f"(a), "=f"(b) : "l"(v));
}

// monotone float<->uint key for atomicMax on floats
__device__ __forceinline__ unsigned int fkey(float f) {
    unsigned int u = __float_as_uint(f);
    return (u & 0x80000000u) ? ~u : (u | 0x80000000u);
}
__device__ __forceinline__ float fdecode(unsigned int u) {
    return __uint_as_float((u & 0x80000000u) ? (u & 0x7FFFFFFFu) : ~u);
}

// ---------------- kernels ----------------

// zero flags; zero whole output (pooled keys start at 0 == key(-inf-ish))
__global__ void k_reset(unsigned int* out, int out_n) {
    int i = blockIdx.x * blockDim.x + threadIdx.x;
    int stride = gridDim.x * blockDim.x;
    for (int j = i; j < NCELL; j += stride) g_flags[j] = 0;
    for (int j = i; j < out_n; j += stride) out[j] = 0u;
}

__global__ void k_mark(const int* __restrict__ xy) {
    int p = blockIdx.x * blockDim.x + threadIdx.x;
    if (p < PTOT) {
        int2 v = ((const int2*)xy)[p];
        int b = p / NPTS;
        int cell = (b * GRIDW + v.x) * GRIDW + v.y;
        g_flags[cell] = 1;
    }
}

// per-block exclusive scan of flags (900 blocks x 1024)
__global__ void k_scan1() {
    __shared__ int ws[32];
    int i = blockIdx.x * 1024 + threadIdx.x;
    int lane = threadIdx.x & 31, wid = threadIdx.x >> 5;
    int v = g_flags[i];
    unsigned int m = __ballot_sync(0xffffffffu, v);
    int excl = __popc(m & ((1u << lane) - 1u));
    if (lane == 31) ws[wid] = excl + v;
    __syncthreads();
    if (wid == 0) {
        int x = ws[lane];
        #pragma unroll
        for (int d = 1; d < 32; d <<= 1) {
            int o = __shfl_up_sync(0xffffffffu, x, d);
            if (lane >= d) x += o;
        }
        ws[lane] = x;
    }
    __syncthreads();
    g_rank[i] = excl + (wid ? ws[wid - 1] : 0);
    if (threadIdx.x == 1023) g_bsum[blockIdx.x] = ws[31];
}

// exclusive scan of 900 block sums (1 block x 1024)
__global__ void k_scan2() {
    __shared__ int ws[32];
    int t = threadIdx.x;
    int lane = t & 31, wid = t >> 5;
    int v = (t < 900) ? g_bsum[t] : 0;
    int s = v;
    #pragma unroll
    for (int d = 1; d < 32; d <<= 1) {
        int o = __shfl_up_sync(0xffffffffu, s, d);
        if (lane >= d) s += o;
    }
    if (lane == 31) ws[wid] = s;
    __syncthreads();
    if (wid == 0) {
        int x = ws[lane];
        #pragma unroll
        for (int d = 1; d < 32; d <<= 1) {
            int o = __shfl_up_sync(0xffffffffu, x, d);
            if (lane >= d) x += o;
        }
        ws[lane] = x;
    }
    __syncthreads();
    int incl = s + (wid ? ws[wid - 1] : 0);
    if (t < 900) g_bsum[t] = incl - v;
}

// finalize ranks + write unq rows (sorted order == dense cell index order)
__global__ void k_scan3(float* unq_out) {
    int i = blockIdx.x * 1024 + threadIdx.x;
    if (g_flags[i]) {
        int r = g_rank[i] + g_bsum[blockIdx.x];
        g_rank[i] = r;
        if (unq_out) {
            int b = i / (GRIDW * GRIDW);
            int rem = i - b * GRIDW * GRIDW;
            unq_out[3 * r + 0] = (float)b;
            unq_out[3 * r + 1] = (float)(rem / GRIDW);
            unq_out[3 * r + 2] = (float)(rem % GRIDW);
        }
    }
}

// fused MLP (3->128->256->64) + atomicMax pooling. Persistent, smem-staged weights.
__global__ void __launch_bounds__(NT, 1)
k_mlp(const float* __restrict__ pt_fea, const int* __restrict__ xy,
      const float* __restrict__ W1, const float* __restrict__ b1,
      const float* __restrict__ W2, const float* __restrict__ b2,
      const float* __restrict__ W3, const float* __restrict__ b3,
      unsigned int* __restrict__ pooled) {
    extern __shared__ float sm[];
    int t = threadIdx.x;

    // weights staged once per block
    for (int i = t; i < 32768; i += NT) sm[S_W2 + i] = W2[i];
    for (int i = t; i < 384; i += NT) sm[S_W1 + i] = W1[i];
    if (t < 128) sm[S_B1 + t] = b1[t];
    if (t < 256) sm[S_B2 + t] = b2[t];
    if (t < 64)  sm[S_B3 + t] = b3[t];

    // L2-phase mapping: 2 points x 8 cols
    const int ptg2 = t & 63;          // point pair group
    const int jg   = t >> 6;          // 0..3 -> 8 j's each
    // L3/epilogue mapping: 4 points x 8 outputs
    const int ptg  = t & 31;
    const int dg   = t >> 5;          // 0..7
    const int d0   = dg * 8;

    for (int tile = blockIdx.x; tile < NTILES; tile += gridDim.x) {
        __syncthreads();  // covers weight load (first iter) + prev-tile smem reuse
        int base = tile * TILE;

        for (int i = t; i < TILE * 3; i += NT) sm[S_XS + i] = pt_fea[base * 3 + i];
        if (t < TILE) {
            int p = base + t;
            int2 v = ((const int2*)xy)[p];
            int b = p / NPTS;
            int cell = (b * GRIDW + v.x) * GRIDW + v.y;
            ((int*)sm)[S_RANK + t] = g_rank[cell];
        }
        __syncthreads();

        // ---- layer 1: h1s[i*128 + pt] ----
        for (int idx = t; idx < 128 * TILE; idx += NT) {
            int i = idx >> 7;
            int pt = idx & 127;
            float x0 = sm[S_XS + pt * 3 + 0];
            float x1 = sm[S_XS + pt * 3 + 1];
            float x2 = sm[S_XS + pt * 3 + 2];
            float v = sm[S_B1 + i];
            v = fmaf(x0, sm[S_W1 + i], v);
            v = fmaf(x1, sm[S_W1 + 128 + i], v);
            v = fmaf(x2, sm[S_W1 + 256 + i], v);
            sm[S_H1 + idx] = fmaxf(v, 0.0f);
        }

        unsigned long long acc3[4][4];
        #pragma unroll
        for (int q = 0; q < 4; q++)
            #pragma unroll
            for (int k = 0; k < 4; k++) acc3[q][k] = 0ull;

        __syncthreads();

        for (int ch = 0; ch < 8; ch++) {
            // stage W3 chunk (rows ch*32 .. +31)
            for (int i = t; i < 2048; i += NT)
                sm[S_W3C + i] = W3[ch * 2048 + i];

            // ---- layer 2: h2 chunk (32 cols), thread tile 2pt x 8j ----
            {
                unsigned long long a2[2][4];
                #pragma unroll
                for (int q = 0; q < 2; q++)
                    #pragma unroll
                    for (int h = 0; h < 4; h++) a2[q][h] = 0ull;

                const float* w2row = sm + S_W2 + ch * 32 + jg * 8;
                const float2* h1v = (const float2*)(sm + S_H1);
                #pragma unroll 4
                for (int i = 0; i < 128; i++) {
                    float2 a = h1v[i * 64 + ptg2];
                    const ulonglong2* wp = (const ulonglong2*)(w2row + i * 256);
                    ulonglong2 wA = wp[0];
                    ulonglong2 wB = wp[1];
                    unsigned long long u0 = dup2(a.x);
                    unsigned long long u1 = dup2(a.y);
                    fma2(a2[0][0], u0, wA.x); fma2(a2[0][1], u0, wA.y);
                    fma2(a2[0][2], u0, wB.x); fma2(a2[0][3], u0, wB.y);
                    fma2(a2[1][0], u1, wA.x); fma2(a2[1][1], u1, wA.y);
                    fma2(a2[1][2], u1, wB.x); fma2(a2[1][3], u1, wB.y);
                }
                // bias + relu + store transposed h2s[jloc][pt]
                #pragma unroll
                for (int h = 0; h < 4; h++) {
                    int jl = jg * 8 + 2 * h;      // local col (even)
                    float ba = sm[S_B2 + ch * 32 + jl];
                    float bb = sm[S_B2 + ch * 32 + jl + 1];
                    float f00, f01, f10, f11;
                    upk2(a2[0][h], f00, f01);
                    upk2(a2[1][h], f10, f11);
                    f00 = fmaxf(f00 + ba, 0.f); f10 = fmaxf(f10 + ba, 0.f);
                    f01 = fmaxf(f01 + bb, 0.f); f11 = fmaxf(f11 + bb, 0.f);
                    ((float2*)(sm + S_H2 + jl * 128))[ptg2] = make_float2(f00, f10);
                    ((float2*)(sm + S_H2 + (jl + 1) * 128))[ptg2] = make_float2(f01, f11);
                }
            }
            __syncthreads();

            // ---- layer 3 accumulate: thread tile 4pt x 8d ----
            {
                #pragma unroll 4
                for (int jl = 0; jl < 32; jl++) {
                    float4 a = *(const float4*)(sm + S_H2 + jl * 128 + ptg * 4);
                    const ulonglong2* wp = (const ulonglong2*)(sm + S_W3C + jl * 64 + d0);
                    ulonglong2 wA = wp[0];
                    ulonglong2 wB = wp[1];
                    unsigned long long u;
                    u = dup2(a.x);
                    fma2(acc3[0][0], u, wA.x); fma2(acc3[0][1], u, wA.y);
                    fma2(acc3[0][2], u, wB.x); fma2(acc3[0][3], u, wB.y);
                    u = dup2(a.y);
                    fma2(acc3[1][0], u, wA.x); fma2(acc3[1][1], u, wA.y);
                    fma2(acc3[1][2], u, wB.x); fma2(acc3[1][3], u, wB.y);
                    u = dup2(a.z);
                    fma2(acc3[2][0], u, wA.x); fma2(acc3[2][1], u, wA.y);
                    fma2(acc3[2][2], u, wB.x); fma2(acc3[2][3], u, wB.y);
                    u = dup2(a.w);
                    fma2(acc3[3][0], u, wA.x); fma2(acc3[3][1], u, wA.y);
                    fma2(acc3[3][2], u, wB.x); fma2(acc3[3][3], u, wB.y);
                }
            }
            __syncthreads();
        }

        // ---- epilogue: bias + atomicMax into pooled[rank*64 + d] ----
        #pragma unroll
        for (int q = 0; q < 4; q++) {
            int r = ((int*)sm)[S_RANK + ptg * 4 + q];
            unsigned int* dst = pooled + (size_t)r * 64 + d0;
            #pragma unroll
            for (int k = 0; k < 4; k++) {
                float f0, f1;
                upk2(acc3[q][k], f0, f1);
                f0 += sm[S_B3 + d0 + 2 * k];
                f1 += sm[S_B3 + d0 + 2 * k + 1];
                atomicMax(dst + 2 * k, fkey(f0));
                atomicMax(dst + 2 * k + 1, fkey(f1));
            }
        }
    }
}

__global__ void k_decode(unsigned int* pooled, int n) {
    int i = blockIdx.x * blockDim.x + threadIdx.x;
    int stride = gridDim.x * blockDim.x;
    for (int j = i; j < n; j += stride)
        ((float*)pooled)[j] = fdecode(pooled[j]);
}

// ---------------- host launcher ----------------
extern "C" void kernel_launch(void* const* d_in, const int* in_sizes, int n_in,
                              void* d_out, int out_size) {
    const float* pt_fea = (const float*)d_in[0];
    const int*   xy     = (const int*)d_in[1];
    const float* W1     = (const float*)d_in[2];
    const float* b1     = (const float*)d_in[3];
    const float* W2     = (const float*)d_in[4];
    const float* b2     = (const float*)d_in[5];
    const float* W3     = (const float*)d_in[6];
    const float* b3     = (const float*)d_in[7];

    int M;
    float* unq_out;
    unsigned int* pooled;
    if (out_size % 67 == 0) {
        M = out_size / 67;
        unq_out = (float*)d_out;
        pooled = (unsigned int*)d_out + 3 * M;
    } else {
        M = out_size / 64;
        unq_out = nullptr;
        pooled = (unsigned int*)d_out;
    }

    cudaFuncSetAttribute(k_mlp, cudaFuncAttributeMaxDynamicSharedMemorySize, SMEM_BYTES);

    k_reset<<<2048, 256>>>((unsigned int*)d_out, out_size);
    k_mark<<<(PTOT + 255) / 256, 256>>>(xy);
    k_scan1<<<NCELL / 1024, 1024>>>();
    k_scan2<<<1, 1024>>>();
    k_scan3<<<NCELL / 1024, 1024>>>(unq_out);
    k_mlp<<<148, NT, SMEM_BYTES>>>(pt_fea, xy, W1, b1, W2, b2, W3, b3, pooled);
    k_decode<<<1024, 256>>>(pooled, M * 64);
}

// round 3
// speedup vs baseline: 4.3250x; 4.3250x over previous
#include <cuda_runtime.h>
#include <cstdint>

#define GRIDW 480
#define NPTS 100000
#define PTOT 400000
#define NCELL (4*GRIDW*GRIDW)      // 921600
#define NSM 148
#define NWARPS (NSM*8)             // 1184
#define NGROUP (PTOT/16)           // 25000 warp-tiles of 16 points

// ---------------- smem layout (u32 offsets) ----------------
#define SW2 0        // W2 B-frags: 32 ns x 16 ks x 32 lane x 2 = 32768 u32
#define SW3 32768    // W3 B-frags: 8 nt x 32 ks x 32 lane x 2 = 16384 u32
#define SW1 49152    // 3*128 f32
#define SB1 49536    // 128
#define SB2 49664    // 256
#define SB3 49920    // 64
#define SMEM_U32 49984
#define SMEM_BYTES (SMEM_U32*4)    // 199936 B

// ---------------- device scratch ----------------
__device__ int g_cnt[NCELL];
__device__ int g_rank[NCELL];     // after scan3: (rank<<1)|solo
__device__ unsigned char g_solo[NCELL];
__device__ int g_bsum[1024];

// ---------------- helpers ----------------
__device__ __forceinline__ uint32_t f2tf(float f) {
    uint32_t u; asm("cvt.rna.tf32.f32 %0, %1;" : "=r"(u) : "f"(f)); return u;
}
__device__ __forceinline__ unsigned int fkey(float f) {
    unsigned int u = __float_as_uint(f);
    return (u & 0x80000000u) ? ~u : (u | 0x80000000u);
}
__device__ __forceinline__ float fdecode(unsigned int u) {
    return __uint_as_float((u & 0x80000000u) ? (u & 0x7FFFFFFFu) : ~u);
}
__device__ __forceinline__ void mma8(float* d, const uint32_t* a, const uint32_t* b) {
    asm volatile("mma.sync.aligned.m16n8k8.row.col.f32.tf32.tf32.f32 "
        "{%0,%1,%2,%3},{%4,%5,%6,%7},{%8,%9},{%0,%1,%2,%3};"
        : "+f"(d[0]), "+f"(d[1]), "+f"(d[2]), "+f"(d[3])
        : "r"(a[0]), "r"(a[1]), "r"(a[2]), "r"(a[3]), "r"(b[0]), "r"(b[1]));
}

// ---------------- small kernels ----------------
__global__ void k_reset(unsigned int* out, int out_n) {
    int i = blockIdx.x * blockDim.x + threadIdx.x;
    int stride = gridDim.x * blockDim.x;
    for (int j = i; j < NCELL; j += stride) g_cnt[j] = 0;
    for (int j = i; j < out_n; j += stride) out[j] = 0u;
}

__global__ void k_mark(const int* __restrict__ xy) {
    int p = blockIdx.x * blockDim.x + threadIdx.x;
    if (p < PTOT) {
        int2 v = ((const int2*)xy)[p];
        int b = p / NPTS;
        atomicAdd(&g_cnt[(b * GRIDW + v.x) * GRIDW + v.y], 1);
    }
}

__global__ void k_scan1() {
    __shared__ int ws[32];
    int i = blockIdx.x * 1024 + threadIdx.x;
    int lane = threadIdx.x & 31, wid = threadIdx.x >> 5;
    int v = (g_cnt[i] != 0);
    unsigned int m = __ballot_sync(0xffffffffu, v);
    int excl = __popc(m & ((1u << lane) - 1u));
    if (lane == 31) ws[wid] = excl + v;
    __syncthreads();
    if (wid == 0) {
        int x = ws[lane];
        #pragma unroll
        for (int d = 1; d < 32; d <<= 1) {
            int o = __shfl_up_sync(0xffffffffu, x, d);
            if (lane >= d) x += o;
        }
        ws[lane] = x;
    }
    __syncthreads();
    g_rank[i] = excl + (wid ? ws[wid - 1] : 0);
    if (threadIdx.x == 1023) g_bsum[blockIdx.x] = ws[31];
}

__global__ void k_scan2() {
    __shared__ int ws[32];
    int t = threadIdx.x;
    int lane = t & 31, wid = t >> 5;
    int v = (t < 900) ? g_bsum[t] : 0;
    int s = v;
    #pragma unroll
    for (int d = 1; d < 32; d <<= 1) {
        int o = __shfl_up_sync(0xffffffffu, s, d);
        if (lane >= d) s += o;
    }
    if (lane == 31) ws[wid] = s;
    __syncthreads();
    if (wid == 0) {
        int x = ws[lane];
        #pragma unroll
        for (int d = 1; d < 32; d <<= 1) {
            int o = __shfl_up_sync(0xffffffffu, x, d);
            if (lane >= d) x += o;
        }
        ws[lane] = x;
    }
    __syncthreads();
    int incl = s + (wid ? ws[wid - 1] : 0);
    if (t < 900) g_bsum[t] = incl - v;
}

__global__ void k_scan3(float* unq_out) {
    int i = blockIdx.x * 1024 + threadIdx.x;
    int c = g_cnt[i];
    if (c) {
        int r = g_rank[i] + g_bsum[blockIdx.x];
        int solo = (c == 1);
        g_rank[i] = (r << 1) | solo;
        g_solo[r] = (unsigned char)solo;
        if (unq_out) {
            int b = i / (GRIDW * GRIDW);
            int rem = i - b * GRIDW * GRIDW;
            unq_out[3 * r + 0] = (float)b;
            unq_out[3 * r + 1] = (float)(rem / GRIDW);
            unq_out[3 * r + 2] = (float)(rem % GRIDW);
        }
    }
}

// ---------------- fused tf32 mma.sync MLP ----------------
__global__ void __launch_bounds__(256, 1)
k_mlp(const float* __restrict__ pt_fea, const int* __restrict__ xy,
      const float* __restrict__ W1g, const float* __restrict__ b1g,
      const float* __restrict__ W2g, const float* __restrict__ b2g,
      const float* __restrict__ W3g, const float* __restrict__ b3g,
      unsigned int* __restrict__ pooled) {
    extern __shared__ uint32_t sm[];
    float* smf = (float*)sm;
    int t = threadIdx.x;

    // ---- stage W2 as B-fragments: sm[SW2 + ((ns*16+ks)*32+lane)*2 + j] ----
    for (int idx = t; idx < 32768; idx += 256) {
        int j = idx & 1, lane = (idx >> 1) & 31, ks = (idx >> 6) & 15, ns = idx >> 10;
        int k = ks * 8 + (lane & 3) + 4 * j;
        int n = ns * 8 + (lane >> 2);
        sm[SW2 + idx] = f2tf(W2g[k * 256 + n]);
    }
    // ---- stage W3 as B-fragments: sm[SW3 + ((nt*32+ks)*32+lane)*2 + j] ----
    for (int idx = t; idx < 16384; idx += 256) {
        int j = idx & 1, lane = (idx >> 1) & 31, ks = (idx >> 6) & 31, nt = idx >> 11;
        int k = ks * 8 + (lane & 3) + 4 * j;
        int n = nt * 8 + (lane >> 2);
        sm[SW3 + idx] = f2tf(W3g[k * 64 + n]);
    }
    for (int i = t; i < 384; i += 256) smf[SW1 + i] = W1g[i];
    if (t < 128) smf[SB1 + t] = b1g[t];
    if (t < 64) { smf[SB2 + t] = b2g[t]; smf[SB2 + 64 + t] = b2g[64 + t];
                  smf[SB2 + 128 + t] = b2g[128 + t]; smf[SB2 + 192 + t] = b2g[192 + t];
                  smf[SB3 + t] = b3g[t]; }
    __syncthreads();

    const int lane = t & 31;
    const int gq = lane >> 2, tig = lane & 3;
    const int warp = (blockIdx.x << 3) + (t >> 5);
    const int lsrc = (lane & 28) | ((lane & 3) >> 1);
    const int hi = lane & 1;

    for (int grp = warp; grp < NGROUP; grp += NWARPS) {
        int base = grp * 16;
        int p0 = base + gq, p1 = p0 + 8;
        float x00 = pt_fea[p0 * 3], x01 = pt_fea[p0 * 3 + 1], x02 = pt_fea[p0 * 3 + 2];
        float x10 = pt_fea[p1 * 3], x11 = pt_fea[p1 * 3 + 1], x12 = pt_fea[p1 * 3 + 2];
        int2 v0 = ((const int2*)xy)[p0];
        int2 v1 = ((const int2*)xy)[p1];
        int r0 = g_rank[((p0 / NPTS) * GRIDW + v0.x) * GRIDW + v0.y];
        int r1 = g_rank[((p1 / NPTS) * GRIDW + v1.x) * GRIDW + v1.y];

        // ---- layer 1 -> A fragments in registers ----
        uint32_t A[16][4];
        #pragma unroll
        for (int ks = 0; ks < 16; ks++) {
            int c0 = ks * 8 + tig, c4 = c0 + 4;
            float w0a = smf[SW1 + c0], w1a = smf[SW1 + 128 + c0], w2a = smf[SW1 + 256 + c0];
            float w0b = smf[SW1 + c4], w1b = smf[SW1 + 128 + c4], w2b = smf[SW1 + 256 + c4];
            float ba = smf[SB1 + c0], bb = smf[SB1 + c4];
            A[ks][0] = f2tf(fmaxf(fmaf(x02, w2a, fmaf(x01, w1a, fmaf(x00, w0a, ba))), 0.f));
            A[ks][1] = f2tf(fmaxf(fmaf(x12, w2a, fmaf(x11, w1a, fmaf(x10, w0a, ba))), 0.f));
            A[ks][2] = f2tf(fmaxf(fmaf(x02, w2b, fmaf(x01, w1b, fmaf(x00, w0b, bb))), 0.f));
            A[ks][3] = f2tf(fmaxf(fmaf(x12, w2b, fmaf(x11, w1b, fmaf(x10, w0b, bb))), 0.f));
        }

        float acc3[8][4];
        #pragma unroll
        for (int n = 0; n < 8; n++)
            #pragma unroll
            for (int q = 0; q < 4; q++) acc3[n][q] = 0.f;

        #pragma unroll 1
        for (int nc = 0; nc < 4; nc++) {
            // ---- layer 2 chunk: 64 output cols ----
            float acc2[8][4];
            #pragma unroll
            for (int n = 0; n < 8; n++)
                #pragma unroll
                for (int q = 0; q < 4; q++) acc2[n][q] = 0.f;

            const uint32_t* w2p = sm + SW2 + nc * 8192 + lane * 2;
            #pragma unroll
            for (int ks = 0; ks < 16; ks++) {
                #pragma unroll
                for (int nt = 0; nt < 8; nt++) {
                    uint32_t b[2];
                    *(uint2*)b = *(const uint2*)(w2p + nt * 1024 + ks * 64);
                    mma8(acc2[nt], A[ks], b);
                }
            }

            // ---- D->A transform (shuffles) + bias/relu + layer 3 partial ----
            const uint32_t* w3p = sm + SW3 + nc * 8 * 64 + lane * 2;
            #pragma unroll
            for (int ks3 = 0; ks3 < 8; ks3++) {
                float c0 = acc2[ks3][0], c1 = acc2[ks3][1];
                float c2 = acc2[ks3][2], c3 = acc2[ks3][3];
                float s0l  = __shfl_sync(0xffffffffu, c0, lsrc);
                float s1l  = __shfl_sync(0xffffffffu, c1, lsrc);
                float s0l2 = __shfl_sync(0xffffffffu, c0, lsrc + 2);
                float s1l2 = __shfl_sync(0xffffffffu, c1, lsrc + 2);
                float s2l  = __shfl_sync(0xffffffffu, c2, lsrc);
                float s3l  = __shfl_sync(0xffffffffu, c3, lsrc);
                float s2l2 = __shfl_sync(0xffffffffu, c2, lsrc + 2);
                float s3l2 = __shfl_sync(0xffffffffu, c3, lsrc + 2);
                float a0 = hi ? s1l : s0l;
                float a2 = hi ? s1l2 : s0l2;
                float a1 = hi ? s3l : s2l;
                float a3 = hi ? s3l2 : s2l2;
                float bc  = smf[SB2 + nc * 64 + ks3 * 8 + tig];
                float bc4 = smf[SB2 + nc * 64 + ks3 * 8 + tig + 4];
                uint32_t af[4];
                af[0] = f2tf(fmaxf(a0 + bc, 0.f));
                af[1] = f2tf(fmaxf(a1 + bc, 0.f));
                af[2] = f2tf(fmaxf(a2 + bc4, 0.f));
                af[3] = f2tf(fmaxf(a3 + bc4, 0.f));
                #pragma unroll
                for (int nt3 = 0; nt3 < 8; nt3++) {
                    uint32_t b[2];
                    *(uint2*)b = *(const uint2*)(w3p + nt3 * 2048 + ks3 * 64);
                    mma8(acc3[nt3], af, b);
                }
            }
        }

        // ---- epilogue: +b3, solo STG fast path or atomicMax(fkey) ----
        #pragma unroll
        for (int half = 0; half < 2; half++) {
            int r = half ? r1 : r0;
            size_t rb = (size_t)(r >> 1) * 64;
            if (r & 1) {
                float* dst = (float*)pooled + rb;
                #pragma unroll
                for (int nt3 = 0; nt3 < 8; nt3++) {
                    int col = nt3 * 8 + 2 * tig;
                    float2 val;
                    val.x = acc3[nt3][2 * half] + smf[SB3 + col];
                    val.y = acc3[nt3][2 * half + 1] + smf[SB3 + col + 1];
                    *(float2*)(dst + col) = val;
                }
            } else {
                unsigned int* dst = pooled + rb;
                #pragma unroll
                for (int nt3 = 0; nt3 < 8; nt3++) {
                    int col = nt3 * 8 + 2 * tig;
                    atomicMax(dst + col,     fkey(acc3[nt3][2 * half] + smf[SB3 + col]));
                    atomicMax(dst + col + 1, fkey(acc3[nt3][2 * half + 1] + smf[SB3 + col + 1]));
                }
            }
        }
    }
}

__global__ void k_decode(unsigned int* pooled, int n) {
    int i = blockIdx.x * blockDim.x + threadIdx.x;
    int stride = gridDim.x * blockDim.x;
    for (int j = i; j < n; j += stride) {
        if (!g_solo[j >> 6]) {
            unsigned int u = pooled[j];
            ((float*)pooled)[j] = fdecode(u);
        }
    }
}

// ---------------- host launcher ----------------
extern "C" void kernel_launch(void* const* d_in, const int* in_sizes, int n_in,
                              void* d_out, int out_size) {
    const float* pt_fea = (const float*)d_in[0];
    const int*   xy     = (const int*)d_in[1];
    const float* W1     = (const float*)d_in[2];
    const float* b1     = (const float*)d_in[3];
    const float* W2     = (const float*)d_in[4];
    const float* b2     = (const float*)d_in[5];
    const float* W3     = (const float*)d_in[6];
    const float* b3     = (const float*)d_in[7];

    int M;
    float* unq_out;
    unsigned int* pooled;
    if (out_size % 67 == 0) {
        M = out_size / 67;
        unq_out = (float*)d_out;
        pooled = (unsigned int*)d_out + (size_t)3 * M;
    } else {
        M = out_size / 64;
        unq_out = nullptr;
        pooled = (unsigned int*)d_out;
    }

    cudaFuncSetAttribute(k_mlp, cudaFuncAttributeMaxDynamicSharedMemorySize, SMEM_BYTES);

    k_reset<<<2048, 256>>>((unsigned int*)d_out, out_size);
    k_mark<<<(PTOT + 255) / 256, 256>>>(xy);
    k_scan1<<<NCELL / 1024, 1024>>>();
    k_scan2<<<1, 1024>>>();
    k_scan3<<<NCELL / 1024, 1024>>>(unq_out);
    k_mlp<<<NSM, 256, SMEM_BYTES>>>(pt_fea, xy, W1, b1, W2, b2, W3, b3, pooled);
    k_decode<<<1024, 256>>>(pooled, M * 64);
}

// round 4
// speedup vs baseline: 7.0954x; 1.6406x over previous
#include <cuda_runtime.h>
#include <cstdint>

#define GRIDW 480
#define NPTS 100000
#define PTOT 400000
#define NCELL (4*GRIDW*GRIDW)      // 921600
#define NSM 148
#define NTHR 384
#define NWARPS (NSM*12)            // 1776
#define NGROUP (PTOT/16)           // 25000 warp-tiles of 16 points

// ---------------- smem layout (u32 offsets) ----------------
#define SW2 0        // W2 B-frags fp16: 4nc x 8ks x 8nt x 64 = 16384 u32
#define SW3 16384    // W3 B-frags fp16: 4nc x 4kt x 8nt x 64 = 8192 u32
#define SW1 24576    // 3*128 f32
#define SB1 24960    // 128
#define SB2 25088    // 256
#define SB3 25344    // 64
#define SMEM_U32 25408
#define SMEM_BYTES (SMEM_U32*4)    // 101632 B

// ---------------- device scratch ----------------
__device__ int g_cnt[NCELL];
__device__ int g_rank[NCELL];     // after scan3: (rank<<1)|solo
__device__ unsigned char g_solo[NCELL];
__device__ int g_bsum[1024];

// ---------------- helpers ----------------
__device__ __forceinline__ uint32_t f2h2(float lo, float hi) {
    uint32_t r;
    asm("cvt.rn.f16x2.f32 %0, %1, %2;" : "=r"(r) : "f"(hi), "f"(lo));
    return r;
}
__device__ __forceinline__ unsigned short f2h(float f) {
    unsigned short h;
    asm("cvt.rn.f16.f32 %0, %1;" : "=h"(h) : "f"(f));
    return h;
}
__device__ __forceinline__ void mma16(float* d, const uint32_t* a, uint32_t b0, uint32_t b1) {
    asm volatile("mma.sync.aligned.m16n8k16.row.col.f32.f16.f16.f32 "
        "{%0,%1,%2,%3},{%4,%5,%6,%7},{%8,%9},{%0,%1,%2,%3};"
        : "+f"(d[0]), "+f"(d[1]), "+f"(d[2]), "+f"(d[3])
        : "r"(a[0]), "r"(a[1]), "r"(a[2]), "r"(a[3]), "r"(b0), "r"(b1));
}
__device__ __forceinline__ void atomic_fmax(float* addr, float v) {
    if (v >= 0.0f) atomicMax((int*)addr, __float_as_int(v));
    else atomicMin((unsigned int*)addr, __float_as_uint(v));
}

// ---------------- small kernels ----------------
__global__ void k_clear() {
    int i = blockIdx.x * blockDim.x + threadIdx.x;
    int stride = gridDim.x * blockDim.x;
    for (int j = i; j < NCELL; j += stride) g_cnt[j] = 0;
}

__global__ void k_mark(const int* __restrict__ xy) {
    int p = blockIdx.x * blockDim.x + threadIdx.x;
    if (p < PTOT) {
        int2 v = ((const int2*)xy)[p];
        int b = p / NPTS;
        atomicAdd(&g_cnt[(b * GRIDW + v.x) * GRIDW + v.y], 1);
    }
}

__global__ void k_scan1() {
    __shared__ int ws[32];
    int i = blockIdx.x * 1024 + threadIdx.x;
    int lane = threadIdx.x & 31, wid = threadIdx.x >> 5;
    int v = (g_cnt[i] != 0);
    unsigned int m = __ballot_sync(0xffffffffu, v);
    int excl = __popc(m & ((1u << lane) - 1u));
    if (lane == 31) ws[wid] = excl + v;
    __syncthreads();
    if (wid == 0) {
        int x = ws[lane];
        #pragma unroll
        for (int d = 1; d < 32; d <<= 1) {
            int o = __shfl_up_sync(0xffffffffu, x, d);
            if (lane >= d) x += o;
        }
        ws[lane] = x;
    }
    __syncthreads();
    g_rank[i] = excl + (wid ? ws[wid - 1] : 0);
    if (threadIdx.x == 1023) g_bsum[blockIdx.x] = ws[31];
}

__global__ void k_scan2() {
    __shared__ int ws[32];
    int t = threadIdx.x;
    int lane = t & 31, wid = t >> 5;
    int v = (t < 900) ? g_bsum[t] : 0;
    int s = v;
    #pragma unroll
    for (int d = 1; d < 32; d <<= 1) {
        int o = __shfl_up_sync(0xffffffffu, s, d);
        if (lane >= d) s += o;
    }
    if (lane == 31) ws[wid] = s;
    __syncthreads();
    if (wid == 0) {
        int x = ws[lane];
        #pragma unroll
        for (int d = 1; d < 32; d <<= 1) {
            int o = __shfl_up_sync(0xffffffffu, x, d);
            if (lane >= d) x += o;
        }
        ws[lane] = x;
    }
    __syncthreads();
    int incl = s + (wid ? ws[wid - 1] : 0);
    if (t < 900) g_bsum[t] = incl - v;
}

__global__ void k_scan3(float* unq_out) {
    int i = blockIdx.x * 1024 + threadIdx.x;
    int c = g_cnt[i];
    if (c) {
        int r = g_rank[i] + g_bsum[blockIdx.x];
        int solo = (c == 1);
        g_rank[i] = (r << 1) | solo;
        g_solo[r] = (unsigned char)solo;
        if (unq_out) {
            int b = i / (GRIDW * GRIDW);
            int rem = i - b * GRIDW * GRIDW;
            unq_out[3 * r + 0] = (float)b;
            unq_out[3 * r + 1] = (float)(rem / GRIDW);
            unq_out[3 * r + 2] = (float)(rem % GRIDW);
        }
    }
}

// init only non-solo pooled rows to -inf (solo rows get fully STG'd by k_mlp)
__global__ void k_init(unsigned int* pooled, int n) {
    int i = blockIdx.x * blockDim.x + threadIdx.x;
    int stride = gridDim.x * blockDim.x;
    for (int j = i; j < n; j += stride)
        if (!g_solo[j >> 6]) pooled[j] = 0xff800000u;
}

// ---------------- fused fp16 mma.sync MLP ----------------
__global__ void __launch_bounds__(NTHR, 1)
k_mlp(const float* __restrict__ pt_fea, const int* __restrict__ xy,
      const float* __restrict__ W1g, const float* __restrict__ b1g,
      const float* __restrict__ W2g, const float* __restrict__ b2g,
      const float* __restrict__ W3g, const float* __restrict__ b3g,
      float* __restrict__ pooled) {
    extern __shared__ uint32_t sm[];
    float* smf = (float*)sm;
    int t = threadIdx.x;

    // ---- stage W2 as fp16 B-frags: sm[SW2 + ((nc*8+ks)*8+nt)*64 + lane*2 + j] ----
    // b-reg j: halves cover k = ks*16 + (lane&3)*2 + j*8 + {0,1}; n = nc*64 + nt*8 + (lane>>2)
    for (int idx = t; idx < 16384; idx += NTHR) {
        int j = idx & 1, lane = (idx >> 1) & 31, nt = (idx >> 6) & 7,
            ks = (idx >> 9) & 7, nc = idx >> 12;
        int k = ks * 16 + (lane & 3) * 2 + j * 8;
        int n = nc * 64 + nt * 8 + (lane >> 2);
        sm[SW2 + idx] = (uint32_t)f2h(W2g[k * 256 + n]) |
                        ((uint32_t)f2h(W2g[(k + 1) * 256 + n]) << 16);
    }
    // ---- stage W3 as fp16 B-frags: sm[SW3 + ((nc*4+kt)*8+nt)*64 + lane*2 + j] ----
    for (int idx = t; idx < 8192; idx += NTHR) {
        int j = idx & 1, lane = (idx >> 1) & 31, nt = (idx >> 6) & 7,
            kt = (idx >> 9) & 3, nc = idx >> 11;
        int k = nc * 64 + kt * 16 + (lane & 3) * 2 + j * 8;
        int n = nt * 8 + (lane >> 2);
        sm[SW3 + idx] = (uint32_t)f2h(W3g[k * 64 + n]) |
                        ((uint32_t)f2h(W3g[(k + 1) * 64 + n]) << 16);
    }
    for (int i = t; i < 384; i += NTHR) smf[SW1 + i] = W1g[i];
    if (t < 128) smf[SB1 + t] = b1g[t];
    if (t < 64) { smf[SB2 + t] = b2g[t]; smf[SB2 + 64 + t] = b2g[64 + t];
                  smf[SB2 + 128 + t] = b2g[128 + t]; smf[SB2 + 192 + t] = b2g[192 + t];
                  smf[SB3 + t] = b3g[t]; }
    __syncthreads();

    const int lane = t & 31;
    const int gq = lane >> 2, tig = lane & 3;
    const int warp = blockIdx.x * (NTHR / 32) + (t >> 5);

    for (int grp = warp; grp < NGROUP; grp += NWARPS) {
        int base = grp * 16;
        int p0 = base + gq, p1 = p0 + 8;
        float x00 = pt_fea[p0 * 3], x01 = pt_fea[p0 * 3 + 1], x02 = pt_fea[p0 * 3 + 2];
        float x10 = pt_fea[p1 * 3], x11 = pt_fea[p1 * 3 + 1], x12 = pt_fea[p1 * 3 + 2];
        int2 v0 = ((const int2*)xy)[p0];
        int2 v1 = ((const int2*)xy)[p1];
        int r0 = g_rank[((p0 / NPTS) * GRIDW + v0.x) * GRIDW + v0.y];
        int r1 = g_rank[((p1 / NPTS) * GRIDW + v1.x) * GRIDW + v1.y];

        // ---- layer 1 -> fp16 A fragments (m16k16): A[ks][0..3] ----
        uint32_t A[8][4];
        #pragma unroll
        for (int ks = 0; ks < 8; ks++) {
            int c0 = ks * 16 + tig * 2;        // a0/a1 halves: c0, c0+1
            int c8 = c0 + 8;                   // a2/a3 halves: c8, c8+1
            #pragma unroll
            for (int h = 0; h < 2; h++) {
                int c = h ? c8 : c0;
                float wa0 = smf[SW1 + c],       wa1 = smf[SW1 + c + 1];
                float wb0 = smf[SW1 + 128 + c], wb1 = smf[SW1 + 128 + c + 1];
                float wc0 = smf[SW1 + 256 + c], wc1 = smf[SW1 + 256 + c + 1];
                float ba = smf[SB1 + c], bb = smf[SB1 + c + 1];
                float p0a = fmaxf(fmaf(x02, wc0, fmaf(x01, wb0, fmaf(x00, wa0, ba))), 0.f);
                float p0b = fmaxf(fmaf(x02, wc1, fmaf(x01, wb1, fmaf(x00, wa1, bb))), 0.f);
                float p1a = fmaxf(fmaf(x12, wc0, fmaf(x11, wb0, fmaf(x10, wa0, ba))), 0.f);
                float p1b = fmaxf(fmaf(x12, wc1, fmaf(x11, wb1, fmaf(x10, wa1, bb))), 0.f);
                A[ks][0 + h * 2] = f2h2(p0a, p0b);
                A[ks][1 + h * 2] = f2h2(p1a, p1b);
            }
        }

        float acc3[8][4];
        #pragma unroll
        for (int n = 0; n < 8; n++)
            #pragma unroll
            for (int q = 0; q < 4; q++) acc3[n][q] = 0.f;

        #pragma unroll 1
        for (int nc = 0; nc < 4; nc++) {
            // ---- layer 2 chunk (64 cols): 64 mma ----
            float acc2[8][4];
            #pragma unroll
            for (int n = 0; n < 8; n++)
                #pragma unroll
                for (int q = 0; q < 4; q++) acc2[n][q] = 0.f;

            const uint32_t* w2p = sm + SW2 + nc * 4096 + lane * 2;
            #pragma unroll
            for (int ks = 0; ks < 8; ks++) {
                #pragma unroll
                for (int nt = 0; nt < 8; nt++) {
                    uint2 b = *(const uint2*)(w2p + (ks * 8 + nt) * 64);
                    mma16(acc2[nt], A[ks], b.x, b.y);
                }
            }

            // ---- bias+relu+pack (D frag == A frag layout; no shuffles) + layer 3 ----
            const uint32_t* w3p = sm + SW3 + nc * 2048 + lane * 2;
            #pragma unroll
            for (int kt = 0; kt < 4; kt++) {
                int ntA = 2 * kt, ntB = 2 * kt + 1;
                float bA0 = smf[SB2 + nc * 64 + ntA * 8 + 2 * tig];
                float bA1 = smf[SB2 + nc * 64 + ntA * 8 + 2 * tig + 1];
                float bB0 = smf[SB2 + nc * 64 + ntB * 8 + 2 * tig];
                float bB1 = smf[SB2 + nc * 64 + ntB * 8 + 2 * tig + 1];
                uint32_t af[4];
                af[0] = f2h2(fmaxf(acc2[ntA][0] + bA0, 0.f), fmaxf(acc2[ntA][1] + bA1, 0.f));
                af[1] = f2h2(fmaxf(acc2[ntA][2] + bA0, 0.f), fmaxf(acc2[ntA][3] + bA1, 0.f));
                af[2] = f2h2(fmaxf(acc2[ntB][0] + bB0, 0.f), fmaxf(acc2[ntB][1] + bB1, 0.f));
                af[3] = f2h2(fmaxf(acc2[ntB][2] + bB0, 0.f), fmaxf(acc2[ntB][3] + bB1, 0.f));
                #pragma unroll
                for (int nt3 = 0; nt3 < 8; nt3++) {
                    uint2 b = *(const uint2*)(w3p + (kt * 8 + nt3) * 64);
                    mma16(acc3[nt3], af, b.x, b.y);
                }
            }
        }

        // ---- epilogue: +b3; solo fast STG, else sign-split atomics ----
        #pragma unroll
        for (int half = 0; half < 2; half++) {
            int r = half ? r1 : r0;
            size_t rb = (size_t)(r >> 1) * 64;
            if (r & 1) {
                float* dst = pooled + rb;
                #pragma unroll
                for (int nt3 = 0; nt3 < 8; nt3++) {
                    int col = nt3 * 8 + 2 * tig;
                    float2 val;
                    val.x = acc3[nt3][2 * half]     + smf[SB3 + col];
                    val.y = acc3[nt3][2 * half + 1] + smf[SB3 + col + 1];
                    *(float2*)(dst + col) = val;
                }
            } else {
                float* dst = pooled + rb;
                #pragma unroll
                for (int nt3 = 0; nt3 < 8; nt3++) {
                    int col = nt3 * 8 + 2 * tig;
                    atomic_fmax(dst + col,     acc3[nt3][2 * half]     + smf[SB3 + col]);
                    atomic_fmax(dst + col + 1, acc3[nt3][2 * half + 1] + smf[SB3 + col + 1]);
                }
            }
        }
    }
}

// ---------------- host launcher ----------------
extern "C" void kernel_launch(void* const* d_in, const int* in_sizes, int n_in,
                              void* d_out, int out_size) {
    const float* pt_fea = (const float*)d_in[0];
    const int*   xy     = (const int*)d_in[1];
    const float* W1     = (const float*)d_in[2];
    const float* b1     = (const float*)d_in[3];
    const float* W2     = (const float*)d_in[4];
    const float* b2     = (const float*)d_in[5];
    const float* W3     = (const float*)d_in[6];
    const float* b3     = (const float*)d_in[7];

    int M;
    float* unq_out;
    float* pooled;
    if (out_size % 67 == 0) {
        M = out_size / 67;
        unq_out = (float*)d_out;
        pooled = (float*)d_out + (size_t)3 * M;
    } else {
        M = out_size / 64;
        unq_out = nullptr;
        pooled = (float*)d_out;
    }

    cudaFuncSetAttribute(k_mlp, cudaFuncAttributeMaxDynamicSharedMemorySize, SMEM_BYTES);

    k_clear<<<1024, 256>>>();
    k_mark<<<(PTOT + 255) / 256, 256>>>(xy);
    k_scan1<<<NCELL / 1024, 1024>>>();
    k_scan2<<<1, 1024>>>();
    k_scan3<<<NCELL / 1024, 1024>>>(unq_out);
    k_init<<<2048, 256>>>((unsigned int*)pooled, M * 64);
    k_mlp<<<NSM, NTHR, SMEM_BYTES>>>(pt_fea, xy, W1, b1, W2, b2, W3, b3, pooled);
}

// round 6
// speedup vs baseline: 7.8675x; 1.1088x over previous
#include <cuda_runtime.h>
#include <cstdint>

#define GRIDW 480
#define NPTS 100000
#define PTOT 400000
#define NCELL (4*GRIDW*GRIDW)      // 921600
#define NSM 148
#define NTHR 512
#define NWARPS (NSM*16)            // 2368
#define NGROUP (PTOT/16)           // 25000 warp-tiles of 16 points

// ---------------- smem layout (u32 offsets) ----------------
#define SW2 0        // W2 B-frags fp16: 4nc x 8ks x 8nt x 64 = 16384 u32
#define SW3 16384    // W3 B-frags fp16: 4nc x 4kt x 8nt x 64 = 8192 u32
#define SW1 24576    // 3*128 f32
#define SB1 24960    // 128
#define SB2 25088    // 256
#define SB3 25344    // 64
#define SMEM_U32 25408
#define SMEM_BYTES (SMEM_U32*4)    // 101632 B

// ---------------- device scratch ----------------
__device__ int g_cnt[NCELL];      // zero at load; self-resetting (scan1 clears)
__device__ int g_rank[NCELL];     // scan1: partial|flags ; scan3: (rank<<1)|solo
__device__ int g_bsum[1024];

// ---------------- helpers ----------------
__device__ __forceinline__ uint32_t f2h2(float lo, float hi) {
    uint32_t r;
    asm("cvt.rn.f16x2.f32 %0, %1, %2;" : "=r"(r) : "f"(hi), "f"(lo));
    return r;
}
__device__ __forceinline__ unsigned short f2h(float f) {
    unsigned short h;
    asm("cvt.rn.f16.f32 %0, %1;" : "=h"(h) : "f"(f));
    return h;
}
__device__ __forceinline__ void mma16(float* d, const uint32_t* a, uint32_t b0, uint32_t b1) {
    asm volatile("mma.sync.aligned.m16n8k16.row.col.f32.f16.f16.f32 "
        "{%0,%1,%2,%3},{%4,%5,%6,%7},{%8,%9},{%0,%1,%2,%3};"
        : "+f"(d[0]), "+f"(d[1]), "+f"(d[2]), "+f"(d[3])
        : "r"(a[0]), "r"(a[1]), "r"(a[2]), "r"(a[3]), "r"(b0), "r"(b1));
}
__device__ __forceinline__ void atomic_fmax(float* addr, float v) {
    if (v >= 0.0f) atomicMax((int*)addr, __float_as_int(v));
    else atomicMin((unsigned int*)addr, __float_as_uint(v));
}

// ---------------- small kernels ----------------
__global__ void k_mark(const int* __restrict__ xy) {
    int p = blockIdx.x * blockDim.x + threadIdx.x;
    if (p < PTOT) {
        int2 v = ((const int2*)xy)[p];
        int b = p / NPTS;
        atomicAdd(&g_cnt[(b * GRIDW + v.x) * GRIDW + v.y], 1);
    }
}

// per-block exclusive scan of occupancy; packs occ/solo flags; zeroes g_cnt for next replay
__global__ void k_scan1() {
    __shared__ int ws[32];
    int i = blockIdx.x * 1024 + threadIdx.x;
    int lane = threadIdx.x & 31, wid = threadIdx.x >> 5;
    int c = g_cnt[i];
    if (c) g_cnt[i] = 0;                    // self-reset (write only if dirty)
    int v = (c != 0);
    unsigned int m = __ballot_sync(0xffffffffu, v);
    int excl = __popc(m & ((1u << lane) - 1u));
    if (lane == 31) ws[wid] = excl + v;
    __syncthreads();
    if (wid == 0) {
        int x = ws[lane];
        #pragma unroll
        for (int d = 1; d < 32; d <<= 1) {
            int o = __shfl_up_sync(0xffffffffu, x, d);
            if (lane >= d) x += o;
        }
        ws[lane] = x;
    }
    __syncthreads();
    int partial = excl + (wid ? ws[wid - 1] : 0);
    g_rank[i] = partial | (v << 16) | ((c == 1) << 17);
    if (threadIdx.x == 1023) g_bsum[blockIdx.x] = ws[31];
}

__global__ void k_scan2() {
    __shared__ int ws[32];
    int t = threadIdx.x;
    int lane = t & 31, wid = t >> 5;
    int v = (t < 900) ? g_bsum[t] : 0;
    int s = v;
    #pragma unroll
    for (int d = 1; d < 32; d <<= 1) {
        int o = __shfl_up_sync(0xffffffffu, s, d);
        if (lane >= d) s += o;
    }
    if (lane == 31) ws[wid] = s;
    __syncthreads();
    if (wid == 0) {
        int x = ws[lane];
        #pragma unroll
        for (int d = 1; d < 32; d <<= 1) {
            int o = __shfl_up_sync(0xffffffffu, x, d);
            if (lane >= d) x += o;
        }
        ws[lane] = x;
    }
    __syncthreads();
    int incl = s + (wid ? ws[wid - 1] : 0);
    if (t < 900) g_bsum[t] = incl - v;
}

// finalize ranks, write unq rows, and -inf-init pooled rows of non-solo voxels.
// NOTE: pooled base is only 8-byte aligned (d_out + 3*M floats, M even) -> uint2 stores.
__global__ void k_scan3(float* unq_out, uint2* pooled) {
    int i = blockIdx.x * 1024 + threadIdx.x;
    int packed = g_rank[i];
    if (packed & (1 << 16)) {
        int solo = (packed >> 17) & 1;
        int r = (packed & 0xFFFF) + g_bsum[blockIdx.x];
        g_rank[i] = (r << 1) | solo;
        if (unq_out) {
            int b = i / (GRIDW * GRIDW);
            int rem = i - b * GRIDW * GRIDW;
            unq_out[3 * r + 0] = (float)b;
            unq_out[3 * r + 1] = (float)(rem / GRIDW);
            unq_out[3 * r + 2] = (float)(rem % GRIDW);
        }
        if (!solo) {
            uint2 ninf = make_uint2(0xff800000u, 0xff800000u);
            uint2* dst = pooled + (size_t)r * 32;
            #pragma unroll
            for (int q = 0; q < 32; q++) dst[q] = ninf;
        }
    }
}

// ---------------- fused fp16 mma.sync MLP ----------------
__global__ void __launch_bounds__(NTHR, 1)
k_mlp(const float* __restrict__ pt_fea, const int* __restrict__ xy,
      const float* __restrict__ W1g, const float* __restrict__ b1g,
      const float* __restrict__ W2g, const float* __restrict__ b2g,
      const float* __restrict__ W3g, const float* __restrict__ b3g,
      float* __restrict__ pooled) {
    extern __shared__ uint32_t sm[];
    float* smf = (float*)sm;
    int t = threadIdx.x;

    // ---- stage W2 as fp16 B-frags: sm[SW2 + ((nc*8+ks)*8+nt)*64 + lane*2 + j] ----
    for (int idx = t; idx < 16384; idx += NTHR) {
        int j = idx & 1, lane = (idx >> 1) & 31, nt = (idx >> 6) & 7,
            ks = (idx >> 9) & 7, nc = idx >> 12;
        int k = ks * 16 + (lane & 3) * 2 + j * 8;
        int n = nc * 64 + nt * 8 + (lane >> 2);
        sm[SW2 + idx] = (uint32_t)f2h(W2g[k * 256 + n]) |
                        ((uint32_t)f2h(W2g[(k + 1) * 256 + n]) << 16);
    }
    // ---- stage W3 as fp16 B-frags: sm[SW3 + ((nc*4+kt)*8+nt)*64 + lane*2 + j] ----
    for (int idx = t; idx < 8192; idx += NTHR) {
        int j = idx & 1, lane = (idx >> 1) & 31, nt = (idx >> 6) & 7,
            kt = (idx >> 9) & 3, nc = idx >> 11;
        int k = nc * 64 + kt * 16 + (lane & 3) * 2 + j * 8;
        int n = nt * 8 + (lane >> 2);
        sm[SW3 + idx] = (uint32_t)f2h(W3g[k * 64 + n]) |
                        ((uint32_t)f2h(W3g[(k + 1) * 64 + n]) << 16);
    }
    for (int i = t; i < 384; i += NTHR) smf[SW1 + i] = W1g[i];
    if (t < 128) smf[SB1 + t] = b1g[t];
    if (t < 64) { smf[SB2 + t] = b2g[t]; smf[SB2 + 64 + t] = b2g[64 + t];
                  smf[SB2 + 128 + t] = b2g[128 + t]; smf[SB2 + 192 + t] = b2g[192 + t];
                  smf[SB3 + t] = b3g[t]; }
    __syncthreads();

    const int lane = t & 31;
    const int gq = lane >> 2, tig = lane & 3;
    const int warp = blockIdx.x * (NTHR / 32) + (t >> 5);

    for (int grp = warp; grp < NGROUP; grp += NWARPS) {
        int base = grp * 16;
        int p0 = base + gq, p1 = p0 + 8;
        float x00 = pt_fea[p0 * 3], x01 = pt_fea[p0 * 3 + 1], x02 = pt_fea[p0 * 3 + 2];
        float x10 = pt_fea[p1 * 3], x11 = pt_fea[p1 * 3 + 1], x12 = pt_fea[p1 * 3 + 2];
        int2 v0 = ((const int2*)xy)[p0];
        int2 v1 = ((const int2*)xy)[p1];
        int r0 = g_rank[((p0 / NPTS) * GRIDW + v0.x) * GRIDW + v0.y];
        int r1 = g_rank[((p1 / NPTS) * GRIDW + v1.x) * GRIDW + v1.y];

        // ---- layer 1 -> fp16 A fragments (m16k16): A[ks][0..3] ----
        uint32_t A[8][4];
        #pragma unroll
        for (int ks = 0; ks < 8; ks++) {
            int c0 = ks * 16 + tig * 2;
            int c8 = c0 + 8;
            #pragma unroll
            for (int h = 0; h < 2; h++) {
                int c = h ? c8 : c0;
                float wa0 = smf[SW1 + c],       wa1 = smf[SW1 + c + 1];
                float wb0 = smf[SW1 + 128 + c], wb1 = smf[SW1 + 128 + c + 1];
                float wc0 = smf[SW1 + 256 + c], wc1 = smf[SW1 + 256 + c + 1];
                float ba = smf[SB1 + c], bb = smf[SB1 + c + 1];
                float p0a = fmaxf(fmaf(x02, wc0, fmaf(x01, wb0, fmaf(x00, wa0, ba))), 0.f);
                float p0b = fmaxf(fmaf(x02, wc1, fmaf(x01, wb1, fmaf(x00, wa1, bb))), 0.f);
                float p1a = fmaxf(fmaf(x12, wc0, fmaf(x11, wb0, fmaf(x10, wa0, ba))), 0.f);
                float p1b = fmaxf(fmaf(x12, wc1, fmaf(x11, wb1, fmaf(x10, wa1, bb))), 0.f);
                A[ks][0 + h * 2] = f2h2(p0a, p0b);
                A[ks][1 + h * 2] = f2h2(p1a, p1b);
            }
        }

        float acc3[8][4];
        #pragma unroll
        for (int n = 0; n < 8; n++)
            #pragma unroll
            for (int q = 0; q < 4; q++) acc3[n][q] = 0.f;

        #pragma unroll 1
        for (int nc = 0; nc < 4; nc++) {
            const uint32_t* w2p = sm + SW2 + nc * 4096 + lane * 2;
            const uint32_t* w3p = sm + SW3 + nc * 2048 + lane * 2;
            // nt-pair outer: acc2 lives only within one pair (8 regs)
            #pragma unroll
            for (int kt = 0; kt < 4; kt++) {
                int ntA = 2 * kt, ntB = 2 * kt + 1;
                float accA[4] = {0.f, 0.f, 0.f, 0.f};
                float accB[4] = {0.f, 0.f, 0.f, 0.f};
                #pragma unroll
                for (int ks = 0; ks < 8; ks++) {
                    uint2 bA = *(const uint2*)(w2p + (ks * 8 + ntA) * 64);
                    mma16(accA, A[ks], bA.x, bA.y);
                    uint2 bB = *(const uint2*)(w2p + (ks * 8 + ntB) * 64);
                    mma16(accB, A[ks], bB.x, bB.y);
                }
                float bA0 = smf[SB2 + nc * 64 + ntA * 8 + 2 * tig];
                float bA1 = smf[SB2 + nc * 64 + ntA * 8 + 2 * tig + 1];
                float bB0 = smf[SB2 + nc * 64 + ntB * 8 + 2 * tig];
                float bB1 = smf[SB2 + nc * 64 + ntB * 8 + 2 * tig + 1];
                uint32_t af[4];
                af[0] = f2h2(fmaxf(accA[0] + bA0, 0.f), fmaxf(accA[1] + bA1, 0.f));
                af[1] = f2h2(fmaxf(accA[2] + bA0, 0.f), fmaxf(accA[3] + bA1, 0.f));
                af[2] = f2h2(fmaxf(accB[0] + bB0, 0.f), fmaxf(accB[1] + bB1, 0.f));
                af[3] = f2h2(fmaxf(accB[2] + bB0, 0.f), fmaxf(accB[3] + bB1, 0.f));
                #pragma unroll
                for (int nt3 = 0; nt3 < 8; nt3++) {
                    uint2 b = *(const uint2*)(w3p + (kt * 8 + nt3) * 64);
                    mma16(acc3[nt3], af, b.x, b.y);
                }
            }
        }

        // ---- epilogue: +b3; solo fast STG, else sign-split atomics ----
        #pragma unroll
        for (int half = 0; half < 2; half++) {
            int r = half ? r1 : r0;
            size_t rb = (size_t)(r >> 1) * 64;
            if (r & 1) {
                float* dst = pooled + rb;
                #pragma unroll
                for (int nt3 = 0; nt3 < 8; nt3++) {
                    int col = nt3 * 8 + 2 * tig;
                    float2 val;
                    val.x = acc3[nt3][2 * half]     + smf[SB3 + col];
                    val.y = acc3[nt3][2 * half + 1] + smf[SB3 + col + 1];
                    *(float2*)(dst + col) = val;
                }
            } else {
                float* dst = pooled + rb;
                #pragma unroll
                for (int nt3 = 0; nt3 < 8; nt3++) {
                    int col = nt3 * 8 + 2 * tig;
                    atomic_fmax(dst + col,     acc3[nt3][2 * half]     + smf[SB3 + col]);
                    atomic_fmax(dst + col + 1, acc3[nt3][2 * half + 1] + smf[SB3 + col + 1]);
                }
            }
        }
    }
}

// ---------------- host launcher ----------------
extern "C" void kernel_launch(void* const* d_in, const int* in_sizes, int n_in,
                              void* d_out, int out_size) {
    const float* pt_fea = (const float*)d_in[0];
    const int*   xy     = (const int*)d_in[1];
    const float* W1     = (const float*)d_in[2];
    const float* b1     = (const float*)d_in[3];
    const float* W2     = (const float*)d_in[4];
    const float* b2     = (const float*)d_in[5];
    const float* W3     = (const float*)d_in[6];
    const float* b3     = (const float*)d_in[7];

    int M;
    float* unq_out;
    float* pooled;
    if (out_size % 67 == 0) {
        M = out_size / 67;
        unq_out = (float*)d_out;
        pooled = (float*)d_out + (size_t)3 * M;
    } else {
        M = out_size / 64;
        unq_out = nullptr;
        pooled = (float*)d_out;
    }

    cudaFuncSetAttribute(k_mlp, cudaFuncAttributeMaxDynamicSharedMemorySize, SMEM_BYTES);

    k_mark<<<(PTOT + 255) / 256, 256>>>(xy);
    k_scan1<<<NCELL / 1024, 1024>>>();
    k_scan2<<<1, 1024>>>();
    k_scan3<<<NCELL / 1024, 1024>>>(unq_out, (uint2*)pooled);
    k_mlp<<<NSM, NTHR, SMEM_BYTES>>>(pt_fea, xy, W1, b1, W2, b2, W3, b3, pooled);
}

// round 7
// speedup vs baseline: 8.2675x; 1.0508x over previous
#include <cuda_runtime.h>
#include <cstdint>

#define GRIDW 480
#define NPTS 100000
#define PTOT 400000
#define NCELL (4*GRIDW*GRIDW)      // 921600
#define NSM 148
#define NTHR 512
#define NWARPS (NSM*16)            // 2368
#define NGROUP (PTOT/16)           // 25000 warp-tiles of 16 points

// ---------------- smem layout (u32 offsets) ----------------
#define SW2 0        // W2 B-frags fp16: 4nc x 8ks x 8nt x 64 = 16384 u32
#define SW3 16384    // W3 B-frags fp16: 4nc x 4kt x 8nt x 64 = 8192 u32
#define SW1 24576    // 3*128 f32
#define SB1 24960    // 128
#define SB2 25088    // 256
#define SB3 25344    // 64
#define SMEM_U32 25408
#define SMEM_BYTES (SMEM_U32*4)    // 101632 B

// ---------------- device scratch ----------------
__device__ int g_cnt[NCELL];      // zero at load; self-resetting (scan1 clears)
__device__ int g_rank[NCELL];     // scan1: partial|flags ; scan3: (rank<<1)|solo
__device__ int g_bsum[1024];

// ---------------- helpers ----------------
__device__ __forceinline__ uint32_t f2h2(float lo, float hi) {
    uint32_t r;
    asm("cvt.rn.f16x2.f32 %0, %1, %2;" : "=r"(r) : "f"(hi), "f"(lo));
    return r;
}
__device__ __forceinline__ unsigned short f2h(float f) {
    unsigned short h;
    asm("cvt.rn.f16.f32 %0, %1;" : "=h"(h) : "f"(f));
    return h;
}
__device__ __forceinline__ void mma16(float* d, const uint32_t* a, uint32_t b0, uint32_t b1) {
    asm volatile("mma.sync.aligned.m16n8k16.row.col.f32.f16.f16.f32 "
        "{%0,%1,%2,%3},{%4,%5,%6,%7},{%8,%9},{%0,%1,%2,%3};"
        : "+f"(d[0]), "+f"(d[1]), "+f"(d[2]), "+f"(d[3])
        : "r"(a[0]), "r"(a[1]), "r"(a[2]), "r"(a[3]), "r"(b0), "r"(b1));
}
__device__ __forceinline__ void atomic_fmax(float* addr, float v) {
    if (v >= 0.0f) atomicMax((int*)addr, __float_as_int(v));
    else atomicMin((unsigned int*)addr, __float_as_uint(v));
}

// ---------------- small kernels ----------------
__global__ void k_mark(const int* __restrict__ xy) {
    int p = blockIdx.x * blockDim.x + threadIdx.x;
    if (p < PTOT) {
        int2 v = ((const int2*)xy)[p];
        int b = p / NPTS;
        atomicAdd(&g_cnt[(b * GRIDW + v.x) * GRIDW + v.y], 1);
    }
}

// per-block exclusive scan of occupancy; packs occ/solo flags; zeroes g_cnt for next replay
__global__ void k_scan1() {
    __shared__ int ws[32];
    int i = blockIdx.x * 1024 + threadIdx.x;
    int lane = threadIdx.x & 31, wid = threadIdx.x >> 5;
    int c = g_cnt[i];
    if (c) g_cnt[i] = 0;                    // self-reset (write only if dirty)
    int v = (c != 0);
    unsigned int m = __ballot_sync(0xffffffffu, v);
    int excl = __popc(m & ((1u << lane) - 1u));
    if (lane == 31) ws[wid] = excl + v;
    __syncthreads();
    if (wid == 0) {
        int x = ws[lane];
        #pragma unroll
        for (int d = 1; d < 32; d <<= 1) {
            int o = __shfl_up_sync(0xffffffffu, x, d);
            if (lane >= d) x += o;
        }
        ws[lane] = x;
    }
    __syncthreads();
    int partial = excl + (wid ? ws[wid - 1] : 0);
    g_rank[i] = partial | (v << 16) | ((c == 1) << 17);
    if (threadIdx.x == 1023) g_bsum[blockIdx.x] = ws[31];
}

// finalize ranks (computing this block's global offset from g_bsum inline),
// write unq rows, and -inf-init pooled rows of non-solo voxels (warp-cooperative).
__global__ void k_scan3(float* unq_out, uint2* pooled) {
    __shared__ int ws[32];
    __shared__ int s_off;
    int t = threadIdx.x;
    int lane = t & 31, wid = t >> 5;

    // ---- block offset = sum of g_bsum[b] for b < blockIdx (900 entries) ----
    int v = (t < blockIdx.x && t < 900) ? g_bsum[t] : 0;
    #pragma unroll
    for (int d = 16; d > 0; d >>= 1)
        v += __shfl_xor_sync(0xffffffffu, v, d);
    if (lane == 0) ws[wid] = v;
    __syncthreads();
    if (wid == 0) {
        int x = ws[lane];
        #pragma unroll
        for (int d = 16; d > 0; d >>= 1)
            x += __shfl_xor_sync(0xffffffffu, x, d);
        if (lane == 0) s_off = x;
    }
    __syncthreads();
    int off = s_off;

    int i = blockIdx.x * 1024 + t;
    int packed = g_rank[i];
    int occ = (packed >> 16) & 1;
    int solo = (packed >> 17) & 1;
    int r = (packed & 0xFFFF) + off;
    if (occ) {
        g_rank[i] = (r << 1) | solo;
        if (unq_out) {
            int b = i / (GRIDW * GRIDW);
            int rem = i - b * GRIDW * GRIDW;
            unq_out[3 * r + 0] = (float)b;
            unq_out[3 * r + 1] = (float)(rem / GRIDW);
            unq_out[3 * r + 2] = (float)(rem % GRIDW);
        }
    }
    // warp-cooperative -inf init of non-solo rows (coalesced 256B per row)
    unsigned int nm = __ballot_sync(0xffffffffu, occ && !solo);
    uint2 ninf = make_uint2(0xff800000u, 0xff800000u);
    while (nm) {
        int src = __ffs(nm) - 1;
        nm &= nm - 1;
        int rr = __shfl_sync(0xffffffffu, r, src);
        pooled[(size_t)rr * 32 + lane] = ninf;
    }
}

// ---------------- fused fp16 mma.sync MLP ----------------
__global__ void __launch_bounds__(NTHR, 1)
k_mlp(const float* __restrict__ pt_fea, const int* __restrict__ xy,
      const float* __restrict__ W1g, const float* __restrict__ b1g,
      const float* __restrict__ W2g, const float* __restrict__ b2g,
      const float* __restrict__ W3g, const float* __restrict__ b3g,
      float* __restrict__ pooled) {
    extern __shared__ uint32_t sm[];
    float* smf = (float*)sm;
    int t = threadIdx.x;

    // ---- stage W2 as fp16 B-frags: sm[SW2 + ((nc*8+ks)*8+nt)*64 + lane*2 + j] ----
    for (int idx = t; idx < 16384; idx += NTHR) {
        int j = idx & 1, lane = (idx >> 1) & 31, nt = (idx >> 6) & 7,
            ks = (idx >> 9) & 7, nc = idx >> 12;
        int k = ks * 16 + (lane & 3) * 2 + j * 8;
        int n = nc * 64 + nt * 8 + (lane >> 2);
        sm[SW2 + idx] = (uint32_t)f2h(W2g[k * 256 + n]) |
                        ((uint32_t)f2h(W2g[(k + 1) * 256 + n]) << 16);
    }
    // ---- stage W3 as fp16 B-frags: sm[SW3 + ((nc*4+kt)*8+nt)*64 + lane*2 + j] ----
    for (int idx = t; idx < 8192; idx += NTHR) {
        int j = idx & 1, lane = (idx >> 1) & 31, nt = (idx >> 6) & 7,
            kt = (idx >> 9) & 3, nc = idx >> 11;
        int k = nc * 64 + kt * 16 + (lane & 3) * 2 + j * 8;
        int n = nt * 8 + (lane >> 2);
        sm[SW3 + idx] = (uint32_t)f2h(W3g[k * 64 + n]) |
                        ((uint32_t)f2h(W3g[(k + 1) * 64 + n]) << 16);
    }
    for (int i = t; i < 384; i += NTHR) smf[SW1 + i] = W1g[i];
    if (t < 128) smf[SB1 + t] = b1g[t];
    if (t < 64) { smf[SB2 + t] = b2g[t]; smf[SB2 + 64 + t] = b2g[64 + t];
                  smf[SB2 + 128 + t] = b2g[128 + t]; smf[SB2 + 192 + t] = b2g[192 + t];
                  smf[SB3 + t] = b3g[t]; }
    __syncthreads();

    const int lane = t & 31;
    const int gq = lane >> 2, tig = lane & 3;
    const int warp = blockIdx.x * (NTHR / 32) + (t >> 5);

    for (int grp = warp; grp < NGROUP; grp += NWARPS) {
        int base = grp * 16;
        int p0 = base + gq, p1 = p0 + 8;
        float x00 = pt_fea[p0 * 3], x01 = pt_fea[p0 * 3 + 1], x02 = pt_fea[p0 * 3 + 2];
        float x10 = pt_fea[p1 * 3], x11 = pt_fea[p1 * 3 + 1], x12 = pt_fea[p1 * 3 + 2];
        int2 v0 = ((const int2*)xy)[p0];
        int2 v1 = ((const int2*)xy)[p1];
        int r0 = g_rank[((p0 / NPTS) * GRIDW + v0.x) * GRIDW + v0.y];
        int r1 = g_rank[((p1 / NPTS) * GRIDW + v1.x) * GRIDW + v1.y];

        // ---- layer 1 -> fp16 A fragments (m16k16): A[ks][0..3] ----
        uint32_t A[8][4];
        #pragma unroll
        for (int ks = 0; ks < 8; ks++) {
            int c0 = ks * 16 + tig * 2;
            int c8 = c0 + 8;
            #pragma unroll
            for (int h = 0; h < 2; h++) {
                int c = h ? c8 : c0;
                float wa0 = smf[SW1 + c],       wa1 = smf[SW1 + c + 1];
                float wb0 = smf[SW1 + 128 + c], wb1 = smf[SW1 + 128 + c + 1];
                float wc0 = smf[SW1 + 256 + c], wc1 = smf[SW1 + 256 + c + 1];
                float ba = smf[SB1 + c], bb = smf[SB1 + c + 1];
                float p0a = fmaxf(fmaf(x02, wc0, fmaf(x01, wb0, fmaf(x00, wa0, ba))), 0.f);
                float p0b = fmaxf(fmaf(x02, wc1, fmaf(x01, wb1, fmaf(x00, wa1, bb))), 0.f);
                float p1a = fmaxf(fmaf(x12, wc0, fmaf(x11, wb0, fmaf(x10, wa0, ba))), 0.f);
                float p1b = fmaxf(fmaf(x12, wc1, fmaf(x11, wb1, fmaf(x10, wa1, bb))), 0.f);
                A[ks][0 + h * 2] = f2h2(p0a, p0b);
                A[ks][1 + h * 2] = f2h2(p1a, p1b);
            }
        }

        float acc3[8][4];
        #pragma unroll
        for (int n = 0; n < 8; n++)
            #pragma unroll
            for (int q = 0; q < 4; q++) acc3[n][q] = 0.f;

        #pragma unroll 1
        for (int nc = 0; nc < 4; nc++) {
            const uint32_t* w2p = sm + SW2 + nc * 4096 + lane * 2;
            const uint32_t* w3p = sm + SW3 + nc * 2048 + lane * 2;
            // nt-pair outer: acc2 lives only within one pair (8 regs)
            #pragma unroll
            for (int kt = 0; kt < 4; kt++) {
                int ntA = 2 * kt, ntB = 2 * kt + 1;
                float accA[4] = {0.f, 0.f, 0.f, 0.f};
                float accB[4] = {0.f, 0.f, 0.f, 0.f};
                #pragma unroll
                for (int ks = 0; ks < 8; ks++) {
                    uint2 bA = *(const uint2*)(w2p + (ks * 8 + ntA) * 64);
                    mma16(accA, A[ks], bA.x, bA.y);
                    uint2 bB = *(const uint2*)(w2p + (ks * 8 + ntB) * 64);
                    mma16(accB, A[ks], bB.x, bB.y);
                }
                float bA0 = smf[SB2 + nc * 64 + ntA * 8 + 2 * tig];
                float bA1 = smf[SB2 + nc * 64 + ntA * 8 + 2 * tig + 1];
                float bB0 = smf[SB2 + nc * 64 + ntB * 8 + 2 * tig];
                float bB1 = smf[SB2 + nc * 64 + ntB * 8 + 2 * tig + 1];
                uint32_t af[4];
                af[0] = f2h2(fmaxf(accA[0] + bA0, 0.f), fmaxf(accA[1] + bA1, 0.f));
                af[1] = f2h2(fmaxf(accA[2] + bA0, 0.f), fmaxf(accA[3] + bA1, 0.f));
                af[2] = f2h2(fmaxf(accB[0] + bB0, 0.f), fmaxf(accB[1] + bB1, 0.f));
                af[3] = f2h2(fmaxf(accB[2] + bB0, 0.f), fmaxf(accB[3] + bB1, 0.f));
                #pragma unroll
                for (int nt3 = 0; nt3 < 8; nt3++) {
                    uint2 b = *(const uint2*)(w3p + (kt * 8 + nt3) * 64);
                    mma16(acc3[nt3], af, b.x, b.y);
                }
            }
        }

        // ---- epilogue: +b3; solo fast STG, else sign-split atomics ----
        #pragma unroll
        for (int half = 0; half < 2; half++) {
            int r = half ? r1 : r0;
            size_t rb = (size_t)(r >> 1) * 64;
            if (r & 1) {
                float* dst = pooled + rb;
                #pragma unroll
                for (int nt3 = 0; nt3 < 8; nt3++) {
                    int col = nt3 * 8 + 2 * tig;
                    float2 val;
                    val.x = acc3[nt3][2 * half]     + smf[SB3 + col];
                    val.y = acc3[nt3][2 * half + 1] + smf[SB3 + col + 1];
                    *(float2*)(dst + col) = val;
                }
            } else {
                float* dst = pooled + rb;
                #pragma unroll
                for (int nt3 = 0; nt3 < 8; nt3++) {
                    int col = nt3 * 8 + 2 * tig;
                    atomic_fmax(dst + col,     acc3[nt3][2 * half]     + smf[SB3 + col]);
                    atomic_fmax(dst + col + 1, acc3[nt3][2 * half + 1] + smf[SB3 + col + 1]);
                }
            }
        }
    }
}

// ---------------- host launcher ----------------
extern "C" void kernel_launch(void* const* d_in, const int* in_sizes, int n_in,
                              void* d_out, int out_size) {
    const float* pt_fea = (const float*)d_in[0];
    const int*   xy     = (const int*)d_in[1];
    const float* W1     = (const float*)d_in[2];
    const float* b1     = (const float*)d_in[3];
    const float* W2     = (const float*)d_in[4];
    const float* b2     = (const float*)d_in[5];
    const float* W3     = (const float*)d_in[6];
    const float* b3     = (const float*)d_in[7];

    int M;
    float* unq_out;
    float* pooled;
    if (out_size % 67 == 0) {
        M = out_size / 67;
        unq_out = (float*)d_out;
        pooled = (float*)d_out + (size_t)3 * M;
    } else {
        M = out_size / 64;
        unq_out = nullptr;
        pooled = (float*)d_out;
    }

    cudaFuncSetAttribute(k_mlp, cudaFuncAttributeMaxDynamicSharedMemorySize, SMEM_BYTES);

    k_mark<<<(PTOT + 255) / 256, 256>>>(xy);
    k_scan1<<<NCELL / 1024, 1024>>>();
    k_scan3<<<NCELL / 1024, 1024>>>(unq_out, (uint2*)pooled);
    k_mlp<<<NSM, NTHR, SMEM_BYTES>>>(pt_fea, xy, W1, b1, W2, b2, W3, b3, pooled);
}